// round 15
// baseline (speedup 1.0000x reference)
#include <cuda_runtime.h>
#include <cuda_bf16.h>
#include <math.h>

// ---------------- problem constants ----------------
#define NTOK   8192
#define LSEQ   1024
#define D_IN   96
#define D_MID  192
#define DI     384
#define NST    16
#define RRANK  12
#define DBL_W  44

typedef unsigned short ushortx;

// ---------------- hi/lo bf16 split helpers ----------------
__device__ __forceinline__ void split2(float x, ushortx &h, ushortx &l){
  __nv_bfloat16 hb = __float2bfloat16_rn(x);
  __nv_bfloat16 lb = __float2bfloat16_rn(x - __bfloat162float(hb));
  h = __bfloat16_as_ushort(hb); l = __bfloat16_as_ushort(lb);
}

// ---------------- scratch ----------------
__device__ ushortx g_xt_h[NTOK*D_IN],  g_xt_l[NTOK*D_IN];
__device__ ushortx g_t1_h[NTOK*D_IN],  g_t1_l[NTOK*D_IN];
__device__ ushortx g_t2_h[NTOK*D_MID], g_t2_l[NTOK*D_MID];
__device__ float   g_xz [NTOK*768];
__device__ ushortx g_xc_h[NTOK*DI],    g_xc_l[NTOK*DI];
__device__ float   g_xc_f[NTOK*DI];
__device__ ushortx g_y_h [NTOK*DI],    g_y_l [NTOK*DI];
__device__ ushortx g_t3_h[NTOK*D_MID], g_t3_l[NTOK*D_MID];
__device__ ushortx g_t4_h[NTOK*D_MID], g_t4_l[NTOK*D_MID];
__device__ float   g_dbl[NTOK*DBL_W];
__device__ float   g_dt [NTOK*DI];
__device__ ushortx g_w1t_h[9*D_IN*D_IN],   g_w1t_l[9*D_IN*D_IN];
__device__ ushortx g_w4t_h[9*D_MID*D_MID], g_w4t_l[9*D_MID*D_MID];
__device__ ushortx g_w2_h[D_MID*D_IN],  g_w2_l[D_MID*D_IN];
__device__ ushortx g_inw_h[768*D_MID],  g_inw_l[768*D_MID];
__device__ ushortx g_xpw_h[DBL_W*DI],   g_xpw_l[DBL_W*DI];
__device__ ushortx g_outw_h[D_MID*DI],  g_outw_l[D_MID*DI];
__device__ ushortx g_w3_h[D_MID*D_MID], g_w3_l[D_MID*D_MID];
__device__ float   g_dtwT[RRANK*DI];
__device__ float   g_bns[768];
__device__ float   g_bnb[768];
__device__ float   g_A  [DI*NST];

// ---------------- activations ----------------
__device__ __forceinline__ float siluf(float x){ return x / (1.0f + __expf(-x)); }
__device__ __forceinline__ float geluf(float x){ return 0.5f*x*(1.0f + erff(x*0.70710678118654752f)); }
__device__ __forceinline__ float softplusf(float x){ return fmaxf(x,0.0f) + log1pf(__expf(-fabsf(x))); }
template<int ACT>
__device__ __forceinline__ float act_apply(float v){
  if (ACT==1) return geluf(v);
  if (ACT==2) return siluf(v);
  return v;
}

// ---------------- mma / async helpers ----------------
__device__ __forceinline__ void ldsm4(unsigned &r0, unsigned &r1, unsigned &r2, unsigned &r3, unsigned addr){
  asm volatile("ldmatrix.sync.aligned.m8n8.x4.shared.b16 {%0,%1,%2,%3}, [%4];"
    : "=r"(r0),"=r"(r1),"=r"(r2),"=r"(r3) : "r"(addr));
}
__device__ __forceinline__ void mma16816(float d[4], const unsigned a[4], unsigned b0, unsigned b1){
  asm volatile("mma.sync.aligned.m16n8k16.row.col.f32.bf16.bf16.f32 "
    "{%0,%1,%2,%3}, {%4,%5,%6,%7}, {%8,%9}, {%0,%1,%2,%3};"
    : "+f"(d[0]),"+f"(d[1]),"+f"(d[2]),"+f"(d[3])
    : "r"(a[0]),"r"(a[1]),"r"(a[2]),"r"(a[3]), "r"(b0),"r"(b1));
}
__device__ __forceinline__ void cp16(unsigned dst, const void* src, bool pred){
  int sz = pred ? 16 : 0;
  asm volatile("cp.async.cg.shared.global [%0], [%1], 16, %2;" :: "r"(dst), "l"(src), "r"(sz));
}
#define CP_COMMIT() asm volatile("cp.async.commit_group;")
#define CP_WAIT1()  asm volatile("cp.async.wait_group 1;")
#define CP_WAIT0()  asm volatile("cp.async.wait_group 0;")

// ---------------- prep ----------------
__global__ void prep_kernel(const float* __restrict__ g1,const float* __restrict__ b1,
                            const float* __restrict__ m1,const float* __restrict__ v1,
                            const float* __restrict__ g2,const float* __restrict__ b2,
                            const float* __restrict__ m2,const float* __restrict__ v2,
                            const float* __restrict__ g3,const float* __restrict__ b3,
                            const float* __restrict__ m3,const float* __restrict__ v3,
                            const float* __restrict__ g4,const float* __restrict__ b4,
                            const float* __restrict__ m4,const float* __restrict__ v4,
                            const float* __restrict__ A_log, const float* __restrict__ dt_w)
{
  int i = blockIdx.x*256 + threadIdx.x;
  const float eps = 1e-5f;
  if (i < 96){  float s = g1[i]*rsqrtf(v1[i]+eps); g_bns[i]     = s; g_bnb[i]     = b1[i]-m1[i]*s; }
  if (i < 192){ float s = g2[i]*rsqrtf(v2[i]+eps); g_bns[192+i] = s; g_bnb[192+i] = b2[i]-m2[i]*s;
                      s = g3[i]*rsqrtf(v3[i]+eps); g_bns[384+i] = s; g_bnb[384+i] = b3[i]-m3[i]*s;
                      s = g4[i]*rsqrtf(v4[i]+eps); g_bns[576+i] = s; g_bnb[576+i] = b4[i]-m4[i]*s; }
  if (i < DI*NST) g_A[i] = -expf(A_log[i]);
  if (i < DI*RRANK){ int d = i/RRANK, r = i - d*RRANK; g_dtwT[r*DI + d] = dt_w[i]; }
}

// ---------------- weight transforms (one launch) ----------------
#define TW1   (D_IN*D_IN*9)
#define TW4   (D_MID*D_MID*9)
#define PK_W2   (D_MID*D_IN)
#define PK_INW  (768*D_MID)
#define PK_XPW  (DBL_W*DI)
#define PK_OUTW (D_MID*DI)
#define PK_W3   (D_MID*D_MID)
#define PW_TOTAL (TW1+TW4+PK_W2+PK_INW+PK_XPW+PK_OUTW+PK_W3)
__global__ void prep_weights(const float* __restrict__ w1, const float* __restrict__ w4,
                             const float* __restrict__ w2, const float* __restrict__ in_w,
                             const float* __restrict__ xp_w, const float* __restrict__ out_w,
                             const float* __restrict__ w3)
{
  int i = blockIdx.x*256 + threadIdx.x;
  int o = i;
  ushortx h,l;
  if (o < TW1){
    int oo = o/(D_IN*9); int r = o - oo*(D_IN*9); int c = r/9; int t = r - c*9;
    split2(w1[o], h, l);
    size_t idx = ((size_t)(t*D_IN + oo))*D_IN + c;
    g_w1t_h[idx] = h; g_w1t_l[idx] = l; return;
  } o -= TW1;
  if (o < TW4){
    int oo = o/(D_MID*9); int r = o - oo*(D_MID*9); int c = r/9; int t = r - c*9;
    split2(w4[o], h, l);
    size_t idx = ((size_t)(t*D_MID + oo))*D_MID + c;
    g_w4t_h[idx] = h; g_w4t_l[idx] = l; return;
  } o -= TW4;
  if (o < PK_W2){ split2(w2[o], h, l); g_w2_h[o]=h; g_w2_l[o]=l; return; }  o -= PK_W2;
  if (o < PK_INW){ split2(in_w[o], h, l); g_inw_h[o]=h; g_inw_l[o]=l; return; } o -= PK_INW;
  if (o < PK_XPW){ split2(xp_w[o], h, l); g_xpw_h[o]=h; g_xpw_l[o]=l; return; } o -= PK_XPW;
  if (o < PK_OUTW){ split2(out_w[o], h, l); g_outw_h[o]=h; g_outw_l[o]=l; return; } o -= PK_OUTW;
  if (o < PK_W3){ split2(w3[o], h, l); g_w3_h[o]=h; g_w3_l[o]=l; }
}

// ---------------- transpose NCHW -> token-major planes ----------------
__global__ void transpose_in(const float* __restrict__ x)
{
  __shared__ float tile[32][33];
  int bc = blockIdx.x, bl = blockIdx.y, b = blockIdx.z;
  int tx = threadIdx.x, ty = threadIdx.y;
  #pragma unroll
  for (int i = ty; i < 32; i += 8)
    tile[i][tx] = x[(b*D_IN + bc*32 + i)*LSEQ + bl*32 + tx];
  __syncthreads();
  #pragma unroll
  for (int i = ty; i < 32; i += 8){
    ushortx h,l; split2(tile[tx][i], h, l);
    size_t idx = (size_t)(b*LSEQ + bl*32 + i)*D_IN + bc*32 + tx;
    g_xt_h[idx] = h; g_xt_l[idx] = l;
  }
}

// ---------------- tile config ----------------
#define BM 64
#define BN 64
#define BKC 32
#define BKP 40
#define NSTAGE 3

// Compute body: hoist ALL ldsm (both ks halves) before the 24 MMAs -> 2x ILP
#define MMA_COMPUTE_BODY(cur)                                                          \
  {                                                                                    \
    const unsigned aH = (unsigned)__cvta_generic_to_shared(&sAh[cur][0][0]);           \
    const unsigned aL = (unsigned)__cvta_generic_to_shared(&sAl[cur][0][0]);           \
    const unsigned bH = (unsigned)__cvta_generic_to_shared(&sBh[cur][0][0]);           \
    const unsigned bL = (unsigned)__cvta_generic_to_shared(&sBl[cur][0][0]);           \
    unsigned ah[2][2][4], al[2][2][4], bh[2][4], bl[2][4];                             \
    _Pragma("unroll")                                                                  \
    for (int kh = 0; kh < 2; ++kh){                                                    \
      const int ks = kh*16;                                                            \
      const unsigned oA0 = (unsigned)(((wm +      lrow)*BKP + ks + lcol)*2);           \
      const unsigned oA1 = (unsigned)(((wm + 16 + lrow)*BKP + ks + lcol)*2);           \
      const unsigned oB  = (unsigned)(((wn +      lrow)*BKP + ks + lcol)*2);           \
      ldsm4(ah[kh][0][0],ah[kh][0][1],ah[kh][0][2],ah[kh][0][3], aH + oA0);            \
      ldsm4(ah[kh][1][0],ah[kh][1][1],ah[kh][1][2],ah[kh][1][3], aH + oA1);            \
      ldsm4(al[kh][0][0],al[kh][0][1],al[kh][0][2],al[kh][0][3], aL + oA0);            \
      ldsm4(al[kh][1][0],al[kh][1][1],al[kh][1][2],al[kh][1][3], aL + oA1);            \
      ldsm4(bh[kh][0],bh[kh][1],bh[kh][2],bh[kh][3], bH + oB);                         \
      ldsm4(bl[kh][0],bl[kh][1],bl[kh][2],bl[kh][3], bL + oB);                         \
    }                                                                                  \
    _Pragma("unroll")                                                                  \
    for (int kh = 0; kh < 2; ++kh){                                                    \
      _Pragma("unroll")                                                                \
      for (int mf=0; mf<2; ++mf){                                                      \
        _Pragma("unroll")                                                              \
        for (int nf=0; nf<2; ++nf){                                                    \
          mma16816(d[mf][nf], ah[kh][mf], bh[kh][nf], bh[kh][2+nf]);                   \
          mma16816(d[mf][nf], al[kh][mf], bh[kh][nf], bh[kh][2+nf]);                   \
          mma16816(d[mf][nf], ah[kh][mf], bl[kh][nf], bl[kh][2+nf]);                   \
        }                                                                              \
      }                                                                                \
    }                                                                                  \
  }

#define PIPE_MAINLOOP()                                                                \
  issue(0, 0);                                                                         \
  if (nch > 1) issue(1, 1);                                                            \
  for (int c = 0; c < nch; ++c){                                                       \
    if (c + 1 < nch) { CP_WAIT1(); } else { CP_WAIT0(); }                              \
    __syncthreads();                                                                   \
    if (c + 2 < nch) issue(c+2, (c+2)%NSTAGE);                                         \
    MMA_COMPUTE_BODY(c % NSTAGE);                                                      \
  }

// =====================================================================
// hi/lo-plane NT GEMM
// =====================================================================
template<int ACT, bool OUTP>
__global__ void __launch_bounds__(256)
gemm_nt(const ushortx* __restrict__ Ahp, const ushortx* __restrict__ Alp, int lda,
        const ushortx* __restrict__ Bhp, const ushortx* __restrict__ Blp,
        void* __restrict__ Ch, void* __restrict__ Cl,
        int N, int K,
        const float* __restrict__ scale, const float* __restrict__ shift)
{
  __shared__ __align__(16) ushortx sAh[NSTAGE][BM][BKP], sAl[NSTAGE][BM][BKP],
                                   sBh[NSTAGE][BN][BKP], sBl[NSTAGE][BN][BKP];
  const int tid  = threadIdx.x;
  const int lane = tid & 31;
  const int warp = tid >> 5;
  const int row0 = blockIdx.x * BM;
  const int col0 = blockIdx.y * BN;
  const int wm = (warp >> 2) * 32;
  const int wn = (warp &  3) * 16;

  float d[2][2][4];
  #pragma unroll
  for (int i=0;i<2;i++)
    #pragma unroll
    for (int j=0;j<2;j++)
      { d[i][j][0]=0.f; d[i][j][1]=0.f; d[i][j][2]=0.f; d[i][j][3]=0.f; }

  const int lrw = tid >> 2;
  const int lpc = (tid & 3) * 8;
  const bool jv = (col0 + lrw) < N;
  const int lrow = lane & 15, lcol = (lane >> 4) * 8;

  const int nch = K / BKC;

  auto issue = [&](int c, int buf){
    const ushortx* a0 = Ahp + (size_t)(row0 + lrw)*lda + c*BKC + lpc;
    const ushortx* a1 = Alp + (size_t)(row0 + lrw)*lda + c*BKC + lpc;
    const ushortx* b0 = Bhp + (size_t)(col0 + lrw)*K   + c*BKC + lpc;
    const ushortx* b1 = Blp + (size_t)(col0 + lrw)*K   + c*BKC + lpc;
    cp16((unsigned)__cvta_generic_to_shared(&sAh[buf][lrw][lpc]), a0, true);
    cp16((unsigned)__cvta_generic_to_shared(&sAl[buf][lrw][lpc]), a1, true);
    cp16((unsigned)__cvta_generic_to_shared(&sBh[buf][lrw][lpc]), b0, jv);
    cp16((unsigned)__cvta_generic_to_shared(&sBl[buf][lrw][lpc]), b1, jv);
    CP_COMMIT();
  };

  PIPE_MAINLOOP();

  const int lr = lane >> 2;
  const int lc = (lane & 3) * 2;
  #pragma unroll
  for (int mf=0; mf<2; ++mf){
    #pragma unroll
    for (int nf=0; nf<2; ++nf){
      int gm = row0 + wm + mf*16 + lr;
      int gn = col0 + wn + nf*8 + lc;
      if (gn < N){
        float sc0 = scale ? scale[gn]   : 1.f;
        float sb0 = shift ? shift[gn]   : 0.f;
        float sc1 = scale ? scale[gn+1] : 1.f;
        float sb1 = shift ? shift[gn+1] : 0.f;
        #pragma unroll
        for (int rr=0; rr<2; ++rr){
          int m = gm + rr*8;
          float o0 = act_apply<ACT>(d[mf][nf][2*rr+0]*sc0 + sb0);
          float o1 = act_apply<ACT>(d[mf][nf][2*rr+1]*sc1 + sb1);
          size_t idx = (size_t)m*N + gn;
          if (OUTP){
            ushortx h0,l0,h1,l1;
            split2(o0,h0,l0); split2(o1,h1,l1);
            ((unsigned*)Ch)[idx>>1] = (unsigned)h0 | ((unsigned)h1<<16);
            ((unsigned*)Cl)[idx>>1] = (unsigned)l0 | ((unsigned)l1<<16);
          } else {
            *(float2*)&((float*)Ch)[idx] = make_float2(o0, o1);
          }
        }
      }
    }
  }
}

// =====================================================================
// 3x3 conv implicit GEMM
// =====================================================================
template<int ACT, bool NCHW_OUT, int CIN>
__global__ void __launch_bounds__(256)
conv3x3_gemm(const ushortx* __restrict__ Xh, const ushortx* __restrict__ Xl,
             const ushortx* __restrict__ Wh, const ushortx* __restrict__ Wl,
             void* __restrict__ Ch, void* __restrict__ Cl,
             int N,
             const float* __restrict__ scale, const float* __restrict__ shift)
{
  __shared__ __align__(16) ushortx sAh[NSTAGE][BM][BKP], sAl[NSTAGE][BM][BKP],
                                   sBh[NSTAGE][BN][BKP], sBl[NSTAGE][BN][BKP];
  const int tid  = threadIdx.x;
  const int lane = tid & 31;
  const int warp = tid >> 5;
  const int row0 = blockIdx.x * BM;
  const int col0 = blockIdx.y * BN;
  const int wm = (warp >> 2) * 32;
  const int wn = (warp &  3) * 16;

  float d[2][2][4];
  #pragma unroll
  for (int i=0;i<2;i++)
    #pragma unroll
    for (int j=0;j<2;j++)
      { d[i][j][0]=0.f; d[i][j][1]=0.f; d[i][j][2]=0.f; d[i][j][3]=0.f; }

  const int lrw = tid >> 2;
  const int lpc = (tid & 3) * 8;
  const bool jv = (col0 + lrw) < N;

  const int gt = row0 + lrw;
  const int bb = gt >> 10;
  const int ll = gt & 1023;
  const int hh = ll >> 5, ww = ll & 31;
  const int lrow = lane & 15, lcol = (lane >> 4) * 8;

  constexpr int kpt = CIN / BKC;
  const int nch = 9 * kpt;

  auto issue = [&](int c, int buf){
    int tap = c / kpt;
    int c0  = (c - tap*kpt) * BKC;
    int t3  = tap / 3;
    int dy  = t3 - 1, dx = tap - t3*3 - 1;
    int nh  = hh + dy, nw = ww + dx;
    bool valid = ((unsigned)nh < 32u) && ((unsigned)nw < 32u);
    int nh2 = valid ? nh : 0, nw2 = valid ? nw : 0;
    size_t aoff = (size_t)((bb<<10) + (nh2<<5) + nw2)*CIN + c0 + lpc;
    size_t boff = ((size_t)(tap*N + (jv ? (col0 + lrw) : col0)))*CIN + c0 + lpc;
    cp16((unsigned)__cvta_generic_to_shared(&sAh[buf][lrw][lpc]), Xh + aoff, valid);
    cp16((unsigned)__cvta_generic_to_shared(&sAl[buf][lrw][lpc]), Xl + aoff, valid);
    cp16((unsigned)__cvta_generic_to_shared(&sBh[buf][lrw][lpc]), Wh + boff, jv);
    cp16((unsigned)__cvta_generic_to_shared(&sBl[buf][lrw][lpc]), Wl + boff, jv);
    CP_COMMIT();
  };

  PIPE_MAINLOOP();

  const int lr = lane >> 2;
  const int lc = (lane & 3) * 2;
  #pragma unroll
  for (int mf=0; mf<2; ++mf){
    #pragma unroll
    for (int nf=0; nf<2; ++nf){
      int gm = row0 + wm + mf*16 + lr;
      int gn = col0 + wn + nf*8 + lc;
      if (gn < N){
        float sc0 = scale ? scale[gn]   : 1.f;
        float sb0 = shift ? shift[gn]   : 0.f;
        float sc1 = scale ? scale[gn+1] : 1.f;
        float sb1 = shift ? shift[gn+1] : 0.f;
        #pragma unroll
        for (int rr=0; rr<2; ++rr){
          int m = gm + rr*8;
          float o0 = act_apply<ACT>(d[mf][nf][2*rr+0]*sc0 + sb0);
          float o1 = act_apply<ACT>(d[mf][nf][2*rr+1]*sc1 + sb1);
          if (NCHW_OUT){
            int ob = m >> 10, ol = m & 1023;
            ((float*)Ch)[(size_t)(ob*N + gn  )*LSEQ + ol] = o0;
            ((float*)Ch)[(size_t)(ob*N + gn+1)*LSEQ + ol] = o1;
          } else {
            ushortx h0,l0,h1,l1;
            split2(o0,h0,l0); split2(o1,h1,l1);
            size_t idx = (size_t)m*N + gn;
            ((unsigned*)Ch)[idx>>1] = (unsigned)h0 | ((unsigned)h1<<16);
            ((unsigned*)Cl)[idx>>1] = (unsigned)l0 | ((unsigned)l1<<16);
          }
        }
      }
    }
  }
}

// ---------------- causal depthwise conv (K=4) + SiLU ----------------
__global__ void dwconv_silu(const float* __restrict__ cw, const float* __restrict__ cb)
{
  int idx = blockIdx.x*256 + threadIdx.x;
  if (idx >= NTOK*DI) return;
  int d = idx % DI;
  int tok = idx / DI;
  int b = tok >> 10, l = tok & 1023;
  float acc = cb[d];
  const float* xi = g_xz + (size_t)(b<<10)*768 + d;
  #pragma unroll
  for (int k=0;k<4;++k){
    int ll = l + k - 3;
    if (ll >= 0) acc = fmaf(xi[(size_t)ll*768], cw[d*4+k], acc);
  }
  float v = siluf(acc);
  ushortx h,lo; split2(v, h, lo);
  g_xc_h[idx] = h; g_xc_l[idx] = lo;
  g_xc_f[idx] = v;
}

// ---------------- dt-proj (K=12) + softplus ----------------
__global__ void dtproj_kernel(const float* __restrict__ dt_b)
{
  int idx = blockIdx.x*256 + threadIdx.x;
  if (idx >= NTOK*DI) return;
  int d = idx % DI;
  int t = idx / DI;
  const float* row = g_dbl + (size_t)t*DBL_W;
  float acc = dt_b[d];
  #pragma unroll
  for (int r=0;r<RRANK;++r)
    acc = fmaf(__ldg(row + r), g_dtwT[r*DI + d], acc);
  g_dt[idx] = softplusf(acc);
}

// =====================================================================
// selective scan — 16-step blocked, sync-free inner loop.
// =====================================================================
__global__ void __launch_bounds__(128)
scan_kernel(const float* __restrict__ Dp)
{
  int gid = (blockIdx.x * 128 + threadIdx.x) >> 4;
  int n   = threadIdx.x & 15;
  int b   = gid / DI;
  int d   = gid - b*DI;
  float Aval = g_A[d*NST + n];
  float dpv  = Dp[d];
  float h = 0.f;
  const float* __restrict__ dtp = g_dt   + (size_t)(b<<10)*DI + d;
  const float* __restrict__ xcp = g_xc_f + (size_t)(b<<10)*DI + d;
  const float* __restrict__ zp  = g_xz   + (size_t)(b<<10)*768 + 384 + d;
  const float* __restrict__ blp = g_dbl  + (size_t)(b<<10)*DBL_W;
  size_t yb = (size_t)(b<<10)*DI + d;

  for (int l0 = 0; l0 < LSEQ; l0 += 16){
    float v[16];
    #pragma unroll
    for (int i = 0; i < 16; ++i){
      int l = l0 + i;
      float dtv = dtp[(size_t)l*DI];
      float xcv = xcp[(size_t)l*DI];
      float Bv  = blp[(size_t)l*DBL_W + RRANK + n];
      float Cv  = blp[(size_t)l*DBL_W + RRANK + NST + n];
      float dA  = __expf(dtv * Aval);
      h = fmaf(dA, h, dtv*Bv*xcv);
      v[i] = h * Cv;
    }
    #pragma unroll
    for (int t = 0; t < 8; ++t){
      float keep = (n & 8) ? v[t+8] : v[t];
      float send = (n & 8) ? v[t]   : v[t+8];
      v[t] = keep + __shfl_xor_sync(0xffffffffu, send, 8, 16);
    }
    #pragma unroll
    for (int t = 0; t < 4; ++t){
      float keep = (n & 4) ? v[t+4] : v[t];
      float send = (n & 4) ? v[t]   : v[t+4];
      v[t] = keep + __shfl_xor_sync(0xffffffffu, send, 4, 16);
    }
    #pragma unroll
    for (int t = 0; t < 2; ++t){
      float keep = (n & 2) ? v[t+2] : v[t];
      float send = (n & 2) ? v[t]   : v[t+2];
      v[t] = keep + __shfl_xor_sync(0xffffffffu, send, 2, 16);
    }
    {
      float keep = (n & 1) ? v[1] : v[0];
      float send = (n & 1) ? v[0] : v[1];
      v[0] = keep + __shfl_xor_sync(0xffffffffu, send, 1, 16);
    }
    {
      int l = l0 + n;
      float xcv = xcp[(size_t)l*DI];
      float zv  = zp[(size_t)l*768];
      ushortx hh2, ll2; split2((v[0] + xcv*dpv) * siluf(zv), hh2, ll2);
      size_t yi = yb + (size_t)l*DI;
      g_y_h[yi] = hh2; g_y_l[yi] = ll2;
    }
  }
}

// ---------------- host launcher ----------------
extern "C" void kernel_launch(void* const* d_in, const int* in_sizes, int n_in,
                              void* d_out, int out_size)
{
  (void)in_sizes; (void)n_in; (void)out_size;
  const float* x    = (const float*)d_in[0];
  const float* w1   = (const float*)d_in[1];
  const float* g1   = (const float*)d_in[2];
  const float* b1   = (const float*)d_in[3];
  const float* m1   = (const float*)d_in[4];
  const float* v1   = (const float*)d_in[5];
  const float* w2   = (const float*)d_in[6];
  const float* g2   = (const float*)d_in[7];
  const float* b2   = (const float*)d_in[8];
  const float* m2   = (const float*)d_in[9];
  const float* v2   = (const float*)d_in[10];
  const float* in_w = (const float*)d_in[11];
  const float* cw   = (const float*)d_in[12];
  const float* cb   = (const float*)d_in[13];
  const float* xp_w = (const float*)d_in[14];
  const float* dt_w = (const float*)d_in[15];
  const float* dt_b = (const float*)d_in[16];
  const float* A_log= (const float*)d_in[17];
  const float* Dp   = (const float*)d_in[18];
  const float* out_w= (const float*)d_in[19];
  const float* w3   = (const float*)d_in[20];
  const float* g3   = (const float*)d_in[21];
  const float* b3   = (const float*)d_in[22];
  const float* m3   = (const float*)d_in[23];
  const float* v3   = (const float*)d_in[24];
  const float* w4   = (const float*)d_in[25];
  const float* g4   = (const float*)d_in[26];
  const float* b4   = (const float*)d_in[27];
  const float* m4   = (const float*)d_in[28];
  const float* v4   = (const float*)d_in[29];

  ushortx *xt_h,*xt_l,*t1_h,*t1_l,*t2_h,*t2_l,*xc_h,*xc_l,*y_h,*y_l,*t3_h,*t3_l,*t4_h,*t4_l;
  ushortx *w1t_h,*w1t_l,*w4t_h,*w4t_l,*w2h,*w2l,*inwh,*inwl,*xpwh,*xpwl,*outwh,*outwl,*w3h,*w3l;
  float *p_xz,*p_dbl,*p_bns,*p_bnb;
  cudaGetSymbolAddress((void**)&xt_h, g_xt_h); cudaGetSymbolAddress((void**)&xt_l, g_xt_l);
  cudaGetSymbolAddress((void**)&t1_h, g_t1_h); cudaGetSymbolAddress((void**)&t1_l, g_t1_l);
  cudaGetSymbolAddress((void**)&t2_h, g_t2_h); cudaGetSymbolAddress((void**)&t2_l, g_t2_l);
  cudaGetSymbolAddress((void**)&p_xz, g_xz);
  cudaGetSymbolAddress((void**)&xc_h, g_xc_h); cudaGetSymbolAddress((void**)&xc_l, g_xc_l);
  cudaGetSymbolAddress((void**)&y_h , g_y_h ); cudaGetSymbolAddress((void**)&y_l , g_y_l );
  cudaGetSymbolAddress((void**)&t3_h, g_t3_h); cudaGetSymbolAddress((void**)&t3_l, g_t3_l);
  cudaGetSymbolAddress((void**)&t4_h, g_t4_h); cudaGetSymbolAddress((void**)&t4_l, g_t4_l);
  cudaGetSymbolAddress((void**)&w1t_h, g_w1t_h); cudaGetSymbolAddress((void**)&w1t_l, g_w1t_l);
  cudaGetSymbolAddress((void**)&w4t_h, g_w4t_h); cudaGetSymbolAddress((void**)&w4t_l, g_w4t_l);
  cudaGetSymbolAddress((void**)&w2h, g_w2_h); cudaGetSymbolAddress((void**)&w2l, g_w2_l);
  cudaGetSymbolAddress((void**)&inwh, g_inw_h); cudaGetSymbolAddress((void**)&inwl, g_inw_l);
  cudaGetSymbolAddress((void**)&xpwh, g_xpw_h); cudaGetSymbolAddress((void**)&xpwl, g_xpw_l);
  cudaGetSymbolAddress((void**)&outwh, g_outw_h); cudaGetSymbolAddress((void**)&outwl, g_outw_l);
  cudaGetSymbolAddress((void**)&w3h, g_w3_h); cudaGetSymbolAddress((void**)&w3l, g_w3_l);
  cudaGetSymbolAddress((void**)&p_dbl, g_dbl);
  cudaGetSymbolAddress((void**)&p_bns, g_bns);
  cudaGetSymbolAddress((void**)&p_bnb, g_bnb);

  // conv1 at my 0-based launch #3 (ncu-captured slot)
  prep_kernel<<<24,256>>>(g1,b1,m1,v1, g2,b2,m2,v2, g3,b3,m3,v3, g4,b4,m4,v4, A_log, dt_w); // #0
  transpose_in<<<dim3(3,32,8), dim3(32,8)>>>(x);                                             // #1
  prep_weights<<<(PW_TOTAL+255)/256,256>>>(w1, w4, w2, in_w, xp_w, out_w, w3);               // #2
  conv3x3_gemm<1,false,D_IN><<<dim3(NTOK/BM, 2),256>>>(xt_h, xt_l, w1t_h, w1t_l, t1_h, t1_l, D_IN, p_bns+0, p_bnb+0); // #3

  gemm_nt<2,true><<<dim3(NTOK/BM, 3),256>>>(t1_h, t1_l, D_IN, w2h, w2l, t2_h, t2_l, D_MID, D_IN, p_bns+192, p_bnb+192);
  gemm_nt<0,false><<<dim3(NTOK/BM, 12),256>>>(t2_h, t2_l, D_MID, inwh, inwl, p_xz, nullptr, 768, D_MID, nullptr, nullptr);
  dwconv_silu<<<(NTOK*DI)/256,256>>>(cw, cb);
  gemm_nt<0,false><<<dim3(NTOK/BM, 1),256>>>(xc_h, xc_l, DI, xpwh, xpwl, p_dbl, nullptr, DBL_W, DI, nullptr, nullptr);
  dtproj_kernel<<<(NTOK*DI)/256,256>>>(dt_b);
  scan_kernel<<<(NTOK/LSEQ)*DI*16/128,128>>>(Dp);
  gemm_nt<0,true><<<dim3(NTOK/BM, 3),256>>>(y_h, y_l, DI, outwh, outwl, t3_h, t3_l, D_MID, DI, nullptr, nullptr);
  gemm_nt<2,true><<<dim3(NTOK/BM, 3),256>>>(t3_h, t3_l, D_MID, w3h, w3l, t4_h, t4_l, D_MID, D_MID, p_bns+384, p_bnb+384);
  conv3x3_gemm<1,true,D_MID><<<dim3(NTOK/BM, 3),256>>>(t4_h, t4_l, w4t_h, w4t_l, (float*)d_out, nullptr, D_MID, p_bns+576, p_bnb+576);
}

// round 16
// speedup vs baseline: 1.0088x; 1.0088x over previous
#include <cuda_runtime.h>
#include <cuda_bf16.h>
#include <math.h>

// ---------------- problem constants ----------------
#define NTOK   8192
#define LSEQ   1024
#define D_IN   96
#define D_MID  192
#define DI     384
#define NST    16
#define RRANK  12
#define DBL_W  44

typedef unsigned short ushortx;

// ---------------- hi/lo bf16 split helpers ----------------
__device__ __forceinline__ void split2(float x, ushortx &h, ushortx &l){
  __nv_bfloat16 hb = __float2bfloat16_rn(x);
  __nv_bfloat16 lb = __float2bfloat16_rn(x - __bfloat162float(hb));
  h = __bfloat16_as_ushort(hb); l = __bfloat16_as_ushort(lb);
}

// ---------------- scratch ----------------
__device__ ushortx g_xt_h[NTOK*D_IN],  g_xt_l[NTOK*D_IN];
__device__ ushortx g_t1_h[NTOK*D_IN],  g_t1_l[NTOK*D_IN];
__device__ ushortx g_t2_h[NTOK*D_MID], g_t2_l[NTOK*D_MID];
__device__ float   g_xz [NTOK*768];
__device__ ushortx g_xc_h[NTOK*DI],    g_xc_l[NTOK*DI];
__device__ float   g_xc_f[NTOK*DI];
__device__ ushortx g_y_h [NTOK*DI],    g_y_l [NTOK*DI];
__device__ ushortx g_t3_h[NTOK*D_MID], g_t3_l[NTOK*D_MID];
__device__ ushortx g_t4_h[NTOK*D_MID], g_t4_l[NTOK*D_MID];
__device__ float   g_c4a[NTOK*D_MID];     // conv4 split-K fp32 accumulator (token-major)
__device__ float   g_dbl[NTOK*DBL_W];
__device__ float   g_dt [NTOK*DI];
__device__ ushortx g_w1t_h[9*D_IN*D_IN],   g_w1t_l[9*D_IN*D_IN];
__device__ ushortx g_w4t_h[9*D_MID*D_MID], g_w4t_l[9*D_MID*D_MID];
__device__ ushortx g_w2_h[D_MID*D_IN],  g_w2_l[D_MID*D_IN];
__device__ ushortx g_inw_h[768*D_MID],  g_inw_l[768*D_MID];
__device__ ushortx g_xpw_h[DBL_W*DI],   g_xpw_l[DBL_W*DI];
__device__ ushortx g_outw_h[D_MID*DI],  g_outw_l[D_MID*DI];
__device__ ushortx g_w3_h[D_MID*D_MID], g_w3_l[D_MID*D_MID];
__device__ float   g_dtwT[RRANK*DI];
__device__ float   g_bns[768];
__device__ float   g_bnb[768];
__device__ float   g_A  [DI*NST];

// ---------------- activations ----------------
__device__ __forceinline__ float siluf(float x){ return x / (1.0f + __expf(-x)); }
__device__ __forceinline__ float geluf(float x){ return 0.5f*x*(1.0f + erff(x*0.70710678118654752f)); }
__device__ __forceinline__ float softplusf(float x){ return fmaxf(x,0.0f) + log1pf(__expf(-fabsf(x))); }
template<int ACT>
__device__ __forceinline__ float act_apply(float v){
  if (ACT==1) return geluf(v);
  if (ACT==2) return siluf(v);
  return v;
}

// ---------------- mma / async helpers ----------------
__device__ __forceinline__ void ldsm4(unsigned &r0, unsigned &r1, unsigned &r2, unsigned &r3, unsigned addr){
  asm volatile("ldmatrix.sync.aligned.m8n8.x4.shared.b16 {%0,%1,%2,%3}, [%4];"
    : "=r"(r0),"=r"(r1),"=r"(r2),"=r"(r3) : "r"(addr));
}
__device__ __forceinline__ void mma16816(float d[4], const unsigned a[4], unsigned b0, unsigned b1){
  asm volatile("mma.sync.aligned.m16n8k16.row.col.f32.bf16.bf16.f32 "
    "{%0,%1,%2,%3}, {%4,%5,%6,%7}, {%8,%9}, {%0,%1,%2,%3};"
    : "+f"(d[0]),"+f"(d[1]),"+f"(d[2]),"+f"(d[3])
    : "r"(a[0]),"r"(a[1]),"r"(a[2]),"r"(a[3]), "r"(b0),"r"(b1));
}
__device__ __forceinline__ void cp16(unsigned dst, const void* src, bool pred){
  int sz = pred ? 16 : 0;
  asm volatile("cp.async.cg.shared.global [%0], [%1], 16, %2;" :: "r"(dst), "l"(src), "r"(sz));
}
#define CP_COMMIT() asm volatile("cp.async.commit_group;")
#define CP_WAIT1()  asm volatile("cp.async.wait_group 1;")
#define CP_WAIT0()  asm volatile("cp.async.wait_group 0;")

// ---------------- prep ----------------
__global__ void prep_kernel(const float* __restrict__ g1,const float* __restrict__ b1,
                            const float* __restrict__ m1,const float* __restrict__ v1,
                            const float* __restrict__ g2,const float* __restrict__ b2,
                            const float* __restrict__ m2,const float* __restrict__ v2,
                            const float* __restrict__ g3,const float* __restrict__ b3,
                            const float* __restrict__ m3,const float* __restrict__ v3,
                            const float* __restrict__ g4,const float* __restrict__ b4,
                            const float* __restrict__ m4,const float* __restrict__ v4,
                            const float* __restrict__ A_log, const float* __restrict__ dt_w)
{
  int i = blockIdx.x*256 + threadIdx.x;
  const float eps = 1e-5f;
  if (i < 96){  float s = g1[i]*rsqrtf(v1[i]+eps); g_bns[i]     = s; g_bnb[i]     = b1[i]-m1[i]*s; }
  if (i < 192){ float s = g2[i]*rsqrtf(v2[i]+eps); g_bns[192+i] = s; g_bnb[192+i] = b2[i]-m2[i]*s;
                      s = g3[i]*rsqrtf(v3[i]+eps); g_bns[384+i] = s; g_bnb[384+i] = b3[i]-m3[i]*s;
                      s = g4[i]*rsqrtf(v4[i]+eps); g_bns[576+i] = s; g_bnb[576+i] = b4[i]-m4[i]*s; }
  if (i < DI*NST) g_A[i] = -expf(A_log[i]);
  if (i < DI*RRANK){ int d = i/RRANK, r = i - d*RRANK; g_dtwT[r*DI + d] = dt_w[i]; }
}

// ---------------- weight transforms (one launch) ----------------
#define TW1   (D_IN*D_IN*9)
#define TW4   (D_MID*D_MID*9)
#define PK_W2   (D_MID*D_IN)
#define PK_INW  (768*D_MID)
#define PK_XPW  (DBL_W*DI)
#define PK_OUTW (D_MID*DI)
#define PK_W3   (D_MID*D_MID)
#define PW_TOTAL (TW1+TW4+PK_W2+PK_INW+PK_XPW+PK_OUTW+PK_W3)
__global__ void prep_weights(const float* __restrict__ w1, const float* __restrict__ w4,
                             const float* __restrict__ w2, const float* __restrict__ in_w,
                             const float* __restrict__ xp_w, const float* __restrict__ out_w,
                             const float* __restrict__ w3)
{
  int i = blockIdx.x*256 + threadIdx.x;
  int o = i;
  ushortx h,l;
  if (o < TW1){
    int oo = o/(D_IN*9); int r = o - oo*(D_IN*9); int c = r/9; int t = r - c*9;
    split2(w1[o], h, l);
    size_t idx = ((size_t)(t*D_IN + oo))*D_IN + c;
    g_w1t_h[idx] = h; g_w1t_l[idx] = l; return;
  } o -= TW1;
  if (o < TW4){
    int oo = o/(D_MID*9); int r = o - oo*(D_MID*9); int c = r/9; int t = r - c*9;
    split2(w4[o], h, l);
    size_t idx = ((size_t)(t*D_MID + oo))*D_MID + c;
    g_w4t_h[idx] = h; g_w4t_l[idx] = l; return;
  } o -= TW4;
  if (o < PK_W2){ split2(w2[o], h, l); g_w2_h[o]=h; g_w2_l[o]=l; return; }  o -= PK_W2;
  if (o < PK_INW){ split2(in_w[o], h, l); g_inw_h[o]=h; g_inw_l[o]=l; return; } o -= PK_INW;
  if (o < PK_XPW){ split2(xp_w[o], h, l); g_xpw_h[o]=h; g_xpw_l[o]=l; return; } o -= PK_XPW;
  if (o < PK_OUTW){ split2(out_w[o], h, l); g_outw_h[o]=h; g_outw_l[o]=l; return; } o -= PK_OUTW;
  if (o < PK_W3){ split2(w3[o], h, l); g_w3_h[o]=h; g_w3_l[o]=l; }
}

// ---------------- transpose NCHW -> token-major planes ----------------
__global__ void transpose_in(const float* __restrict__ x)
{
  __shared__ float tile[32][33];
  int bc = blockIdx.x, bl = blockIdx.y, b = blockIdx.z;
  int tx = threadIdx.x, ty = threadIdx.y;
  #pragma unroll
  for (int i = ty; i < 32; i += 8)
    tile[i][tx] = x[(b*D_IN + bc*32 + i)*LSEQ + bl*32 + tx];
  __syncthreads();
  #pragma unroll
  for (int i = ty; i < 32; i += 8){
    ushortx h,l; split2(tile[tx][i], h, l);
    size_t idx = (size_t)(b*LSEQ + bl*32 + i)*D_IN + bc*32 + tx;
    g_xt_h[idx] = h; g_xt_l[idx] = l;
  }
}

// ---------------- conv4 finish: BN + GELU + token-major -> NCHW ----------------
__global__ void c4_finish(float* __restrict__ out)
{
  __shared__ float tile[32][33];
  int ct = blockIdx.x;   // channel tile 0..5
  int lt = blockIdx.y;   // l tile 0..31
  int b  = blockIdx.z;   // batch 0..7
  int tx = threadIdx.x, ty = threadIdx.y;
  #pragma unroll
  for (int i = ty; i < 32; i += 8){
    int c = ct*32 + tx;
    float v = g_c4a[(size_t)(b*LSEQ + lt*32 + i)*D_MID + c];
    tile[i][tx] = geluf(v * g_bns[576 + c] + g_bnb[576 + c]);
  }
  __syncthreads();
  #pragma unroll
  for (int i = ty; i < 32; i += 8)
    out[(size_t)(b*D_MID + ct*32 + i)*LSEQ + lt*32 + tx] = tile[tx][i];
}

// ---------------- tile config ----------------
#define BM 64
#define BN 64
#define BKC 32
#define BKP 40
#define NSTAGE 3

#define MMA_COMPUTE_BODY(cur)                                                          \
  {                                                                                    \
    const unsigned aH = (unsigned)__cvta_generic_to_shared(&sAh[cur][0][0]);           \
    const unsigned aL = (unsigned)__cvta_generic_to_shared(&sAl[cur][0][0]);           \
    const unsigned bH = (unsigned)__cvta_generic_to_shared(&sBh[cur][0][0]);           \
    const unsigned bL = (unsigned)__cvta_generic_to_shared(&sBl[cur][0][0]);           \
    unsigned ah[2][2][4], al[2][2][4], bh[2][4], bl[2][4];                             \
    _Pragma("unroll")                                                                  \
    for (int kh = 0; kh < 2; ++kh){                                                    \
      const int ks = kh*16;                                                            \
      const unsigned oA0 = (unsigned)(((wm +      lrow)*BKP + ks + lcol)*2);           \
      const unsigned oA1 = (unsigned)(((wm + 16 + lrow)*BKP + ks + lcol)*2);           \
      const unsigned oB  = (unsigned)(((wn +      lrow)*BKP + ks + lcol)*2);           \
      ldsm4(ah[kh][0][0],ah[kh][0][1],ah[kh][0][2],ah[kh][0][3], aH + oA0);            \
      ldsm4(ah[kh][1][0],ah[kh][1][1],ah[kh][1][2],ah[kh][1][3], aH + oA1);            \
      ldsm4(al[kh][0][0],al[kh][0][1],al[kh][0][2],al[kh][0][3], aL + oA0);            \
      ldsm4(al[kh][1][0],al[kh][1][1],al[kh][1][2],al[kh][1][3], aL + oA1);            \
      ldsm4(bh[kh][0],bh[kh][1],bh[kh][2],bh[kh][3], bH + oB);                         \
      ldsm4(bl[kh][0],bl[kh][1],bl[kh][2],bl[kh][3], bL + oB);                         \
    }                                                                                  \
    _Pragma("unroll")                                                                  \
    for (int kh = 0; kh < 2; ++kh){                                                    \
      _Pragma("unroll")                                                                \
      for (int mf=0; mf<2; ++mf){                                                      \
        _Pragma("unroll")                                                              \
        for (int nf=0; nf<2; ++nf){                                                    \
          mma16816(d[mf][nf], ah[kh][mf], bh[kh][nf], bh[kh][2+nf]);                   \
          mma16816(d[mf][nf], al[kh][mf], bh[kh][nf], bh[kh][2+nf]);                   \
          mma16816(d[mf][nf], ah[kh][mf], bl[kh][nf], bl[kh][2+nf]);                   \
        }                                                                              \
      }                                                                                \
    }                                                                                  \
  }

#define PIPE_MAINLOOP()                                                                \
  issue(0, 0);                                                                         \
  if (nch > 1) issue(1, 1);                                                            \
  for (int c = 0; c < nch; ++c){                                                       \
    if (c + 1 < nch) { CP_WAIT1(); } else { CP_WAIT0(); }                              \
    __syncthreads();                                                                   \
    if (c + 2 < nch) issue(c+2, (c+2)%NSTAGE);                                         \
    MMA_COMPUTE_BODY(c % NSTAGE);                                                      \
  }

// =====================================================================
// hi/lo-plane NT GEMM
// =====================================================================
template<int ACT, bool OUTP>
__global__ void __launch_bounds__(256)
gemm_nt(const ushortx* __restrict__ Ahp, const ushortx* __restrict__ Alp, int lda,
        const ushortx* __restrict__ Bhp, const ushortx* __restrict__ Blp,
        void* __restrict__ Ch, void* __restrict__ Cl,
        int N, int K,
        const float* __restrict__ scale, const float* __restrict__ shift)
{
  __shared__ __align__(16) ushortx sAh[NSTAGE][BM][BKP], sAl[NSTAGE][BM][BKP],
                                   sBh[NSTAGE][BN][BKP], sBl[NSTAGE][BN][BKP];
  const int tid  = threadIdx.x;
  const int lane = tid & 31;
  const int warp = tid >> 5;
  const int row0 = blockIdx.x * BM;
  const int col0 = blockIdx.y * BN;
  const int wm = (warp >> 2) * 32;
  const int wn = (warp &  3) * 16;

  float d[2][2][4];
  #pragma unroll
  for (int i=0;i<2;i++)
    #pragma unroll
    for (int j=0;j<2;j++)
      { d[i][j][0]=0.f; d[i][j][1]=0.f; d[i][j][2]=0.f; d[i][j][3]=0.f; }

  const int lrw = tid >> 2;
  const int lpc = (tid & 3) * 8;
  const bool jv = (col0 + lrw) < N;
  const int lrow = lane & 15, lcol = (lane >> 4) * 8;

  const int nch = K / BKC;

  auto issue = [&](int c, int buf){
    const ushortx* a0 = Ahp + (size_t)(row0 + lrw)*lda + c*BKC + lpc;
    const ushortx* a1 = Alp + (size_t)(row0 + lrw)*lda + c*BKC + lpc;
    const ushortx* b0 = Bhp + (size_t)(col0 + lrw)*K   + c*BKC + lpc;
    const ushortx* b1 = Blp + (size_t)(col0 + lrw)*K   + c*BKC + lpc;
    cp16((unsigned)__cvta_generic_to_shared(&sAh[buf][lrw][lpc]), a0, true);
    cp16((unsigned)__cvta_generic_to_shared(&sAl[buf][lrw][lpc]), a1, true);
    cp16((unsigned)__cvta_generic_to_shared(&sBh[buf][lrw][lpc]), b0, jv);
    cp16((unsigned)__cvta_generic_to_shared(&sBl[buf][lrw][lpc]), b1, jv);
    CP_COMMIT();
  };

  PIPE_MAINLOOP();

  const int lr = lane >> 2;
  const int lc = (lane & 3) * 2;
  #pragma unroll
  for (int mf=0; mf<2; ++mf){
    #pragma unroll
    for (int nf=0; nf<2; ++nf){
      int gm = row0 + wm + mf*16 + lr;
      int gn = col0 + wn + nf*8 + lc;
      if (gn < N){
        float sc0 = scale ? scale[gn]   : 1.f;
        float sb0 = shift ? shift[gn]   : 0.f;
        float sc1 = scale ? scale[gn+1] : 1.f;
        float sb1 = shift ? shift[gn+1] : 0.f;
        #pragma unroll
        for (int rr=0; rr<2; ++rr){
          int m = gm + rr*8;
          float o0 = act_apply<ACT>(d[mf][nf][2*rr+0]*sc0 + sb0);
          float o1 = act_apply<ACT>(d[mf][nf][2*rr+1]*sc1 + sb1);
          size_t idx = (size_t)m*N + gn;
          if (OUTP){
            ushortx h0,l0,h1,l1;
            split2(o0,h0,l0); split2(o1,h1,l1);
            ((unsigned*)Ch)[idx>>1] = (unsigned)h0 | ((unsigned)h1<<16);
            ((unsigned*)Cl)[idx>>1] = (unsigned)l0 | ((unsigned)l1<<16);
          } else {
            *(float2*)&((float*)Ch)[idx] = make_float2(o0, o1);
          }
        }
      }
    }
  }
}

// =====================================================================
// 3x3 conv implicit GEMM.
// OUTMODE: 0 = plane out, 2 = fp32 atomicAdd partial (split-K), token-major
// NTAPS taps starting at blockIdx.z*NTAPS.
// =====================================================================
template<int ACT, int OUTMODE, int CIN, int NTAPS>
__global__ void __launch_bounds__(256)
conv3x3_gemm(const ushortx* __restrict__ Xh, const ushortx* __restrict__ Xl,
             const ushortx* __restrict__ Wh, const ushortx* __restrict__ Wl,
             void* __restrict__ Ch, void* __restrict__ Cl,
             int N,
             const float* __restrict__ scale, const float* __restrict__ shift)
{
  __shared__ __align__(16) ushortx sAh[NSTAGE][BM][BKP], sAl[NSTAGE][BM][BKP],
                                   sBh[NSTAGE][BN][BKP], sBl[NSTAGE][BN][BKP];
  const int tid  = threadIdx.x;
  const int lane = tid & 31;
  const int warp = tid >> 5;
  const int row0 = blockIdx.x * BM;
  const int col0 = blockIdx.y * BN;
  const int tap0 = blockIdx.z * NTAPS;
  const int wm = (warp >> 2) * 32;
  const int wn = (warp &  3) * 16;

  float d[2][2][4];
  #pragma unroll
  for (int i=0;i<2;i++)
    #pragma unroll
    for (int j=0;j<2;j++)
      { d[i][j][0]=0.f; d[i][j][1]=0.f; d[i][j][2]=0.f; d[i][j][3]=0.f; }

  const int lrw = tid >> 2;
  const int lpc = (tid & 3) * 8;
  const bool jv = (col0 + lrw) < N;

  const int gt = row0 + lrw;
  const int bb = gt >> 10;
  const int ll = gt & 1023;
  const int hh = ll >> 5, ww = ll & 31;
  const int lrow = lane & 15, lcol = (lane >> 4) * 8;

  constexpr int kpt = CIN / BKC;
  const int nch = NTAPS * kpt;

  auto issue = [&](int c, int buf){
    int tap = tap0 + c / kpt;
    int c0  = (c - (c/kpt)*kpt) * BKC;
    int t3  = tap / 3;
    int dy  = t3 - 1, dx = tap - t3*3 - 1;
    int nh  = hh + dy, nw = ww + dx;
    bool valid = ((unsigned)nh < 32u) && ((unsigned)nw < 32u);
    int nh2 = valid ? nh : 0, nw2 = valid ? nw : 0;
    size_t aoff = (size_t)((bb<<10) + (nh2<<5) + nw2)*CIN + c0 + lpc;
    size_t boff = ((size_t)(tap*N + (jv ? (col0 + lrw) : col0)))*CIN + c0 + lpc;
    cp16((unsigned)__cvta_generic_to_shared(&sAh[buf][lrw][lpc]), Xh + aoff, valid);
    cp16((unsigned)__cvta_generic_to_shared(&sAl[buf][lrw][lpc]), Xl + aoff, valid);
    cp16((unsigned)__cvta_generic_to_shared(&sBh[buf][lrw][lpc]), Wh + boff, jv);
    cp16((unsigned)__cvta_generic_to_shared(&sBl[buf][lrw][lpc]), Wl + boff, jv);
    CP_COMMIT();
  };

  PIPE_MAINLOOP();

  const int lr = lane >> 2;
  const int lc = (lane & 3) * 2;
  #pragma unroll
  for (int mf=0; mf<2; ++mf){
    #pragma unroll
    for (int nf=0; nf<2; ++nf){
      int gm = row0 + wm + mf*16 + lr;
      int gn = col0 + wn + nf*8 + lc;
      if (gn < N){
        float sc0 = scale ? scale[gn]   : 1.f;
        float sb0 = shift ? shift[gn]   : 0.f;
        float sc1 = scale ? scale[gn+1] : 1.f;
        float sb1 = shift ? shift[gn+1] : 0.f;
        #pragma unroll
        for (int rr=0; rr<2; ++rr){
          int m = gm + rr*8;
          size_t idx = (size_t)m*N + gn;
          if (OUTMODE == 2){
            atomicAdd(&((float*)Ch)[idx],   d[mf][nf][2*rr+0]);
            atomicAdd(&((float*)Ch)[idx+1], d[mf][nf][2*rr+1]);
          } else {
            float o0 = act_apply<ACT>(d[mf][nf][2*rr+0]*sc0 + sb0);
            float o1 = act_apply<ACT>(d[mf][nf][2*rr+1]*sc1 + sb1);
            ushortx h0,l0,h1,l1;
            split2(o0,h0,l0); split2(o1,h1,l1);
            ((unsigned*)Ch)[idx>>1] = (unsigned)h0 | ((unsigned)h1<<16);
            ((unsigned*)Cl)[idx>>1] = (unsigned)l0 | ((unsigned)l1<<16);
          }
        }
      }
    }
  }
}

// ---------------- causal depthwise conv (K=4) + SiLU ----------------
__global__ void dwconv_silu(const float* __restrict__ cw, const float* __restrict__ cb)
{
  int idx = blockIdx.x*256 + threadIdx.x;
  if (idx >= NTOK*DI) return;
  int d = idx % DI;
  int tok = idx / DI;
  int b = tok >> 10, l = tok & 1023;
  float acc = cb[d];
  const float* xi = g_xz + (size_t)(b<<10)*768 + d;
  #pragma unroll
  for (int k=0;k<4;++k){
    int ll = l + k - 3;
    if (ll >= 0) acc = fmaf(xi[(size_t)ll*768], cw[d*4+k], acc);
  }
  float v = siluf(acc);
  ushortx h,lo; split2(v, h, lo);
  g_xc_h[idx] = h; g_xc_l[idx] = lo;
  g_xc_f[idx] = v;
}

// ---------------- dt-proj (K=12) + softplus ----------------
__global__ void dtproj_kernel(const float* __restrict__ dt_b)
{
  int idx = blockIdx.x*256 + threadIdx.x;
  if (idx >= NTOK*DI) return;
  int d = idx % DI;
  int t = idx / DI;
  const float* row = g_dbl + (size_t)t*DBL_W;
  float acc = dt_b[d];
  #pragma unroll
  for (int r=0;r<RRANK;++r)
    acc = fmaf(__ldg(row + r), g_dtwT[r*DI + d], acc);
  g_dt[idx] = softplusf(acc);
}

// =====================================================================
// selective scan — 16-step blocked, sync-free inner loop.
// =====================================================================
__global__ void __launch_bounds__(128)
scan_kernel(const float* __restrict__ Dp)
{
  int gid = (blockIdx.x * 128 + threadIdx.x) >> 4;
  int n   = threadIdx.x & 15;
  int b   = gid / DI;
  int d   = gid - b*DI;
  float Aval = g_A[d*NST + n];
  float dpv  = Dp[d];
  float h = 0.f;
  const float* __restrict__ dtp = g_dt   + (size_t)(b<<10)*DI + d;
  const float* __restrict__ xcp = g_xc_f + (size_t)(b<<10)*DI + d;
  const float* __restrict__ zp  = g_xz   + (size_t)(b<<10)*768 + 384 + d;
  const float* __restrict__ blp = g_dbl  + (size_t)(b<<10)*DBL_W;
  size_t yb = (size_t)(b<<10)*DI + d;

  for (int l0 = 0; l0 < LSEQ; l0 += 16){
    float v[16];
    #pragma unroll
    for (int i = 0; i < 16; ++i){
      int l = l0 + i;
      float dtv = dtp[(size_t)l*DI];
      float xcv = xcp[(size_t)l*DI];
      float Bv  = blp[(size_t)l*DBL_W + RRANK + n];
      float Cv  = blp[(size_t)l*DBL_W + RRANK + NST + n];
      float dA  = __expf(dtv * Aval);
      h = fmaf(dA, h, dtv*Bv*xcv);
      v[i] = h * Cv;
    }
    #pragma unroll
    for (int t = 0; t < 8; ++t){
      float keep = (n & 8) ? v[t+8] : v[t];
      float send = (n & 8) ? v[t]   : v[t+8];
      v[t] = keep + __shfl_xor_sync(0xffffffffu, send, 8, 16);
    }
    #pragma unroll
    for (int t = 0; t < 4; ++t){
      float keep = (n & 4) ? v[t+4] : v[t];
      float send = (n & 4) ? v[t]   : v[t+4];
      v[t] = keep + __shfl_xor_sync(0xffffffffu, send, 4, 16);
    }
    #pragma unroll
    for (int t = 0; t < 2; ++t){
      float keep = (n & 2) ? v[t+2] : v[t];
      float send = (n & 2) ? v[t]   : v[t+2];
      v[t] = keep + __shfl_xor_sync(0xffffffffu, send, 2, 16);
    }
    {
      float keep = (n & 1) ? v[1] : v[0];
      float send = (n & 1) ? v[0] : v[1];
      v[0] = keep + __shfl_xor_sync(0xffffffffu, send, 1, 16);
    }
    {
      int l = l0 + n;
      float xcv = xcp[(size_t)l*DI];
      float zv  = zp[(size_t)l*768];
      ushortx hh2, ll2; split2((v[0] + xcv*dpv) * siluf(zv), hh2, ll2);
      size_t yi = yb + (size_t)l*DI;
      g_y_h[yi] = hh2; g_y_l[yi] = ll2;
    }
  }
}

// ---------------- host launcher ----------------
extern "C" void kernel_launch(void* const* d_in, const int* in_sizes, int n_in,
                              void* d_out, int out_size)
{
  (void)in_sizes; (void)n_in; (void)out_size;
  const float* x    = (const float*)d_in[0];
  const float* w1   = (const float*)d_in[1];
  const float* g1   = (const float*)d_in[2];
  const float* b1   = (const float*)d_in[3];
  const float* m1   = (const float*)d_in[4];
  const float* v1   = (const float*)d_in[5];
  const float* w2   = (const float*)d_in[6];
  const float* g2   = (const float*)d_in[7];
  const float* b2   = (const float*)d_in[8];
  const float* m2   = (const float*)d_in[9];
  const float* v2   = (const float*)d_in[10];
  const float* in_w = (const float*)d_in[11];
  const float* cw   = (const float*)d_in[12];
  const float* cb   = (const float*)d_in[13];
  const float* xp_w = (const float*)d_in[14];
  const float* dt_w = (const float*)d_in[15];
  const float* dt_b = (const float*)d_in[16];
  const float* A_log= (const float*)d_in[17];
  const float* Dp   = (const float*)d_in[18];
  const float* out_w= (const float*)d_in[19];
  const float* w3   = (const float*)d_in[20];
  const float* g3   = (const float*)d_in[21];
  const float* b3   = (const float*)d_in[22];
  const float* m3   = (const float*)d_in[23];
  const float* v3   = (const float*)d_in[24];
  const float* w4   = (const float*)d_in[25];
  const float* g4   = (const float*)d_in[26];
  const float* b4   = (const float*)d_in[27];
  const float* m4   = (const float*)d_in[28];
  const float* v4   = (const float*)d_in[29];

  ushortx *xt_h,*xt_l,*t1_h,*t1_l,*t2_h,*t2_l,*xc_h,*xc_l,*y_h,*y_l,*t3_h,*t3_l,*t4_h,*t4_l;
  ushortx *w1t_h,*w1t_l,*w4t_h,*w4t_l,*w2h,*w2l,*inwh,*inwl,*xpwh,*xpwl,*outwh,*outwl,*w3h,*w3l;
  float *p_xz,*p_dbl,*p_bns,*p_bnb,*p_c4a;
  cudaGetSymbolAddress((void**)&xt_h, g_xt_h); cudaGetSymbolAddress((void**)&xt_l, g_xt_l);
  cudaGetSymbolAddress((void**)&t1_h, g_t1_h); cudaGetSymbolAddress((void**)&t1_l, g_t1_l);
  cudaGetSymbolAddress((void**)&t2_h, g_t2_h); cudaGetSymbolAddress((void**)&t2_l, g_t2_l);
  cudaGetSymbolAddress((void**)&p_xz, g_xz);
  cudaGetSymbolAddress((void**)&xc_h, g_xc_h); cudaGetSymbolAddress((void**)&xc_l, g_xc_l);
  cudaGetSymbolAddress((void**)&y_h , g_y_h ); cudaGetSymbolAddress((void**)&y_l , g_y_l );
  cudaGetSymbolAddress((void**)&t3_h, g_t3_h); cudaGetSymbolAddress((void**)&t3_l, g_t3_l);
  cudaGetSymbolAddress((void**)&t4_h, g_t4_h); cudaGetSymbolAddress((void**)&t4_l, g_t4_l);
  cudaGetSymbolAddress((void**)&p_c4a, g_c4a);
  cudaGetSymbolAddress((void**)&w1t_h, g_w1t_h); cudaGetSymbolAddress((void**)&w1t_l, g_w1t_l);
  cudaGetSymbolAddress((void**)&w4t_h, g_w4t_h); cudaGetSymbolAddress((void**)&w4t_l, g_w4t_l);
  cudaGetSymbolAddress((void**)&w2h, g_w2_h); cudaGetSymbolAddress((void**)&w2l, g_w2_l);
  cudaGetSymbolAddress((void**)&inwh, g_inw_h); cudaGetSymbolAddress((void**)&inwl, g_inw_l);
  cudaGetSymbolAddress((void**)&xpwh, g_xpw_h); cudaGetSymbolAddress((void**)&xpwl, g_xpw_l);
  cudaGetSymbolAddress((void**)&outwh, g_outw_h); cudaGetSymbolAddress((void**)&outwl, g_outw_l);
  cudaGetSymbolAddress((void**)&w3h, g_w3_h); cudaGetSymbolAddress((void**)&w3l, g_w3_l);
  cudaGetSymbolAddress((void**)&p_dbl, g_dbl);
  cudaGetSymbolAddress((void**)&p_bns, g_bns);
  cudaGetSymbolAddress((void**)&p_bnb, g_bnb);

  // conv1 at my 0-based launch #3 (ncu-captured slot)
  prep_kernel<<<24,256>>>(g1,b1,m1,v1, g2,b2,m2,v2, g3,b3,m3,v3, g4,b4,m4,v4, A_log, dt_w); // #0
  transpose_in<<<dim3(3,32,8), dim3(32,8)>>>(x);                                             // #1
  prep_weights<<<(PW_TOTAL+255)/256,256>>>(w1, w4, w2, in_w, xp_w, out_w, w3);               // #2
  conv3x3_gemm<1,0,D_IN,9><<<dim3(NTOK/BM, 2, 1),256>>>(xt_h, xt_l, w1t_h, w1t_l, t1_h, t1_l, D_IN, p_bns+0, p_bnb+0); // #3

  // zero conv4 accumulator (memset is graph-capturable, no allocation)
  cudaMemsetAsync(p_c4a, 0, (size_t)NTOK*D_MID*sizeof(float));

  gemm_nt<2,true><<<dim3(NTOK/BM, 3),256>>>(t1_h, t1_l, D_IN, w2h, w2l, t2_h, t2_l, D_MID, D_IN, p_bns+192, p_bnb+192);
  gemm_nt<0,false><<<dim3(NTOK/BM, 12),256>>>(t2_h, t2_l, D_MID, inwh, inwl, p_xz, nullptr, 768, D_MID, nullptr, nullptr);
  dwconv_silu<<<(NTOK*DI)/256,256>>>(cw, cb);
  gemm_nt<0,false><<<dim3(NTOK/BM, 1),256>>>(xc_h, xc_l, DI, xpwh, xpwl, p_dbl, nullptr, DBL_W, DI, nullptr, nullptr);
  dtproj_kernel<<<(NTOK*DI)/256,256>>>(dt_b);
  scan_kernel<<<(NTOK/LSEQ)*DI*16/128,128>>>(Dp);
  gemm_nt<0,true><<<dim3(NTOK/BM, 3),256>>>(y_h, y_l, DI, outwh, outwl, t3_h, t3_l, D_MID, DI, nullptr, nullptr);
  gemm_nt<2,true><<<dim3(NTOK/BM, 3),256>>>(t3_h, t3_l, D_MID, w3h, w3l, t4_h, t4_l, D_MID, D_MID, p_bns+384, p_bnb+384);
  // conv4 split-K over taps (3 slices), fp32 atomic accumulation token-major
  conv3x3_gemm<0,2,D_MID,3><<<dim3(NTOK/BM, 3, 3),256>>>(t4_h, t4_l, w4t_h, w4t_l, p_c4a, nullptr, D_MID, nullptr, nullptr);
  // BN + GELU + coalesced transpose to NCHW
  c4_finish<<<dim3(6,32,8), dim3(32,8)>>>((float*)d_out);
}